// round 2
// baseline (speedup 1.0000x reference)
#include <cuda_runtime.h>
#include <math.h>

#define BB 512
#define TT 1024
#define FF 8
#define H1 70
#define H1P 72
#define G1 280
#define H2 21
#define H2P 24
#define G2 84
#define IN2 140
#define IN2P 144
#define D1 30
#define D2 20
#define H22 42

// Scratch (allocation-free rule: __device__ globals)
__device__ float g_h1[(size_t)BB * TT * IN2];   // layer-1 bi-output, [b][t][140]
__device__ float g_h2[(size_t)BB * TT * H22];   // layer-2 bi-output, [b][t][42]

__device__ __forceinline__ float sigf(float x) {
    return __fdividef(1.0f, 1.0f + __expf(-x));
}
__device__ __forceinline__ float tanhfast(float x) {
    // tanh(x) = 2*sigmoid(2x) - 1
    return fmaf(2.0f, __fdividef(1.0f, 1.0f + __expf(-2.0f * x)), -1.0f);
}

// ---------------------------------------------------------------------------
// Layer 1: one CTA per (batch, direction). 288 threads, thread g owns gate g.
// ---------------------------------------------------------------------------
__global__ __launch_bounds__(288, 2) void lstm1_kernel(
    const float* __restrict__ x,
    const float* __restrict__ wih_f, const float* __restrict__ whh_f,
    const float* __restrict__ bih_f, const float* __restrict__ bhh_f,
    const float* __restrict__ wih_b, const float* __restrict__ whh_b,
    const float* __restrict__ bih_b, const float* __restrict__ bhh_b)
{
    __shared__ float xs[TT * FF];           // 32 KB: whole input row for this batch
    __shared__ __align__(16) float hs[H1P]; // h state (padded, [70..71]=0)
    __shared__ float gs[G1];                // pre-activations

    const int tid = threadIdx.x;
    const int b   = blockIdx.x;
    const int dir = blockIdx.y;

    const float* wih = dir ? wih_b : wih_f;
    const float* whh = dir ? whh_b : whh_f;
    const float* bih = dir ? bih_b : bih_f;
    const float* bhh = dir ? bhh_b : bhh_f;

    // stage x[b, :, :] into smem (coalesced)
    for (int i = tid; i < TT * FF; i += blockDim.x)
        xs[i] = x[(size_t)b * TT * FF + i];
    if (tid < H1P) hs[tid] = 0.0f;

    float wi[FF];
    float wh[H1P];
    float bias = 0.0f;
    if (tid < G1) {
        #pragma unroll
        for (int f = 0; f < FF; f++) wi[f] = wih[tid * FF + f];
        #pragma unroll
        for (int k = 0; k < H1; k++) wh[k] = whh[tid * H1 + k];
        wh[70] = 0.0f; wh[71] = 0.0f;
        bias = bih[tid] + bhh[tid];
    }
    float c = 0.0f;
    __syncthreads();

    for (int t = 0; t < TT; t++) {
        const int tt = dir ? (TT - 1 - t) : t;
        if (tid < G1) {
            float pre = bias;
            const float* xr = &xs[tt * FF];
            #pragma unroll
            for (int f = 0; f < FF; f++) pre = fmaf(wi[f], xr[f], pre);
            const float4* h4 = (const float4*)hs;
            #pragma unroll
            for (int k4 = 0; k4 < H1P / 4; k4++) {
                float4 h = h4[k4];
                pre = fmaf(wh[4 * k4 + 0], h.x, pre);
                pre = fmaf(wh[4 * k4 + 1], h.y, pre);
                pre = fmaf(wh[4 * k4 + 2], h.z, pre);
                pre = fmaf(wh[4 * k4 + 3], h.w, pre);
            }
            gs[tid] = pre;
        }
        __syncthreads();
        if (tid < H1) {
            float gi = sigf(gs[tid]);
            float gf = sigf(gs[H1 + tid]);
            float gg = tanhfast(gs[2 * H1 + tid]);
            float go = sigf(gs[3 * H1 + tid]);
            c = fmaf(gf, c, gi * gg);
            float h = go * tanhfast(c);
            hs[tid] = h;
            g_h1[((size_t)b * TT + tt) * IN2 + dir * H1 + tid] = h;
        }
        __syncthreads();
    }
}

// ---------------------------------------------------------------------------
// Layer 2: one CTA per (batch, direction). 128 threads, thread g owns gate g.
// Input rows (140 floats) from g_h1, software-pipelined double buffer.
// ---------------------------------------------------------------------------
__global__ __launch_bounds__(128, 2) void lstm2_kernel(
    const float* __restrict__ wih_f, const float* __restrict__ whh_f,
    const float* __restrict__ bih_f, const float* __restrict__ bhh_f,
    const float* __restrict__ wih_b, const float* __restrict__ whh_b,
    const float* __restrict__ bih_b, const float* __restrict__ bhh_b)
{
    __shared__ __align__(16) float inbuf[2][IN2P];
    __shared__ __align__(16) float hs[H2P];
    __shared__ float gs[G2];

    const int tid = threadIdx.x;
    const int b   = blockIdx.x;
    const int dir = blockIdx.y;

    const float* wih = dir ? wih_b : wih_f;
    const float* whh = dir ? whh_b : whh_f;
    const float* bih = dir ? bih_b : bih_f;
    const float* bhh = dir ? bhh_b : bhh_f;

    float wi[IN2P];
    float wh[H2P];
    float bias = 0.0f;
    if (tid < G2) {
        #pragma unroll
        for (int k = 0; k < IN2; k++) wi[k] = wih[tid * IN2 + k];
        #pragma unroll
        for (int k = IN2; k < IN2P; k++) wi[k] = 0.0f;
        #pragma unroll
        for (int k = 0; k < H2; k++) wh[k] = whh[tid * H2 + k];
        #pragma unroll
        for (int k = H2; k < H2P; k++) wh[k] = 0.0f;
        bias = bih[tid] + bhh[tid];
    }
    if (tid < H2P) hs[tid] = 0.0f;

    // preload first input row
    {
        const int tt0 = dir ? (TT - 1) : 0;
        const float* row = &g_h1[((size_t)b * TT + tt0) * IN2];
        for (int i = tid; i < IN2P; i += 128)
            inbuf[0][i] = (i < IN2) ? row[i] : 0.0f;
    }
    float c = 0.0f;
    __syncthreads();

    for (int t = 0; t < TT; t++) {
        const int tt  = dir ? (TT - 1 - t) : t;
        const int cur = t & 1;
        const int nxt = cur ^ 1;

        // prefetch next row into registers (latency hidden by compute below)
        float p0 = 0.0f, p1 = 0.0f;
        const bool have_next = (t + 1 < TT);
        if (have_next) {
            const int tn = dir ? (TT - 2 - t) : (t + 1);
            const float* row = &g_h1[((size_t)b * TT + tn) * IN2];
            if (tid < IN2)          p0 = row[tid];
            if (tid + 128 < IN2)    p1 = row[tid + 128];
        }

        if (tid < G2) {
            float pre = bias;
            const float4* in4 = (const float4*)inbuf[cur];
            #pragma unroll
            for (int k4 = 0; k4 < IN2P / 4; k4++) {
                float4 v = in4[k4];
                pre = fmaf(wi[4 * k4 + 0], v.x, pre);
                pre = fmaf(wi[4 * k4 + 1], v.y, pre);
                pre = fmaf(wi[4 * k4 + 2], v.z, pre);
                pre = fmaf(wi[4 * k4 + 3], v.w, pre);
            }
            const float4* h4 = (const float4*)hs;
            #pragma unroll
            for (int k4 = 0; k4 < H2P / 4; k4++) {
                float4 h = h4[k4];
                pre = fmaf(wh[4 * k4 + 0], h.x, pre);
                pre = fmaf(wh[4 * k4 + 1], h.y, pre);
                pre = fmaf(wh[4 * k4 + 2], h.z, pre);
                pre = fmaf(wh[4 * k4 + 3], h.w, pre);
            }
            gs[tid] = pre;
        }
        __syncthreads();
        if (tid < H2) {
            float gi = sigf(gs[tid]);
            float gf = sigf(gs[H2 + tid]);
            float gg = tanhfast(gs[2 * H2 + tid]);
            float go = sigf(gs[3 * H2 + tid]);
            c = fmaf(gf, c, gi * gg);
            float h = go * tanhfast(c);
            hs[tid] = h;
            g_h2[((size_t)b * TT + tt) * H22 + dir * H2 + tid] = h;
        }
        if (have_next) {
            if (tid < IN2P)       inbuf[nxt][tid] = (tid < IN2) ? p0 : 0.0f;
            if (tid + 128 < IN2P) inbuf[nxt][tid + 128] = (tid + 128 < IN2) ? p1 : 0.0f;
        }
        __syncthreads();
    }
}

// ---------------------------------------------------------------------------
// Head MLP: 42 -> 30 relu -> 20 relu -> 1. One thread per (b,t).
// ---------------------------------------------------------------------------
__global__ __launch_bounds__(128) void head_kernel(
    const float* __restrict__ d1w, const float* __restrict__ d1b,
    const float* __restrict__ d2w, const float* __restrict__ d2b,
    const float* __restrict__ ow,  const float* __restrict__ ob,
    float* __restrict__ out)
{
    __shared__ float sv[128 * H22];         // 21.5 KB: 128 h2 rows
    __shared__ float w1[D1 * H22], b1[D1];
    __shared__ float w2[D2 * D1], b2[D2];
    __shared__ float wo[D2];
    __shared__ float obias;

    const int tid = threadIdx.x;
    const size_t base = (size_t)blockIdx.x * 128 * H22;

    for (int i = tid; i < 128 * H22; i += 128) sv[i] = g_h2[base + i];
    for (int i = tid; i < D1 * H22; i += 128) w1[i] = d1w[i];
    if (tid < D1) b1[tid] = d1b[tid];
    for (int i = tid; i < D2 * D1; i += 128) w2[i] = d2w[i];
    if (tid < D2) { b2[tid] = d2b[tid]; wo[tid] = ow[tid]; }
    if (tid == 0) obias = ob[0];
    __syncthreads();

    float v[H22];
    #pragma unroll
    for (int k = 0; k < H22; k++) v[k] = sv[tid * H22 + k];

    float a1[D1];
    #pragma unroll
    for (int j = 0; j < D1; j++) {
        float s = b1[j];
        #pragma unroll
        for (int k = 0; k < H22; k++) s = fmaf(w1[j * H22 + k], v[k], s);
        a1[j] = fmaxf(s, 0.0f);
    }
    float a2[D2];
    #pragma unroll
    for (int j = 0; j < D2; j++) {
        float s = b2[j];
        #pragma unroll
        for (int k = 0; k < D1; k++) s = fmaf(w2[j * D1 + k], a1[k], s);
        a2[j] = fmaxf(s, 0.0f);
    }
    float o = obias;
    #pragma unroll
    for (int k = 0; k < D2; k++) o = fmaf(wo[k], a2[k], o);

    out[(size_t)blockIdx.x * 128 + tid] = o;
}

// ---------------------------------------------------------------------------
extern "C" void kernel_launch(void* const* d_in, const int* in_sizes, int n_in,
                              void* d_out, int out_size)
{
    const float* x       = (const float*)d_in[0];
    const float* wih1_f  = (const float*)d_in[1];
    const float* whh1_f  = (const float*)d_in[2];
    const float* bih1_f  = (const float*)d_in[3];
    const float* bhh1_f  = (const float*)d_in[4];
    const float* wih1_b  = (const float*)d_in[5];
    const float* whh1_b  = (const float*)d_in[6];
    const float* bih1_b  = (const float*)d_in[7];
    const float* bhh1_b  = (const float*)d_in[8];
    const float* wih2_f  = (const float*)d_in[9];
    const float* whh2_f  = (const float*)d_in[10];
    const float* bih2_f  = (const float*)d_in[11];
    const float* bhh2_f  = (const float*)d_in[12];
    const float* wih2_b  = (const float*)d_in[13];
    const float* whh2_b  = (const float*)d_in[14];
    const float* bih2_b  = (const float*)d_in[15];
    const float* bhh2_b  = (const float*)d_in[16];
    const float* d1w     = (const float*)d_in[17];
    const float* d1b     = (const float*)d_in[18];
    const float* d2w     = (const float*)d_in[19];
    const float* d2b     = (const float*)d_in[20];
    const float* ow      = (const float*)d_in[21];
    const float* obv     = (const float*)d_in[22];
    float* out = (float*)d_out;

    dim3 grid_l(BB, 2);
    lstm1_kernel<<<grid_l, 288>>>(x, wih1_f, whh1_f, bih1_f, bhh1_f,
                                  wih1_b, whh1_b, bih1_b, bhh1_b);
    lstm2_kernel<<<grid_l, 128>>>(wih2_f, whh2_f, bih2_f, bhh2_f,
                                  wih2_b, whh2_b, bih2_b, bhh2_b);
    head_kernel<<<(BB * TT) / 128, 128>>>(d1w, d1b, d2w, d2b, ow, obv, out);
}

// round 3
// speedup vs baseline: 1.4429x; 1.4429x over previous
#include <cuda_runtime.h>
#include <math.h>

#define BB 512
#define TT 1024
#define FF 8
#define H1 70
#define H1P 72
#define G1 280
#define H2 21
#define H2P 24
#define G2 84
#define IN2 140
#define IN2P 144
#define D1 30
#define D2 20
#define H22 42

// Scratch (allocation-free rule: __device__ globals)
__device__ float g_h1[(size_t)BB * TT * IN2];   // layer-1 bi-output, [b][t][140]
__device__ float g_h2[(size_t)BB * TT * H22];   // layer-2 bi-output, [b][t][42]

__device__ __forceinline__ float tanha(float x) {
    float y;
    asm("tanh.approx.f32 %0, %1;" : "=f"(y) : "f"(x));
    return y;
}
__device__ __forceinline__ float sigf(float x) {
    return fmaf(0.5f, tanha(0.5f * x), 0.5f);
}

// ---------------------------------------------------------------------------
// Layer 1: one CTA per (batch, direction). 288 threads.
// Lane layout: j = tid>>2 (cell), g = tid&3 (gate). Each thread computes the
// 78-MAC pre-activation for its gate; 3 shfl_down gather the 4 gates to the
// g==0 lane which updates (c,h). Double-buffered h state -> ONE barrier/step.
// ---------------------------------------------------------------------------
__global__ __launch_bounds__(288, 2) void lstm1_kernel(
    const float* __restrict__ x,
    const float* __restrict__ wih_f, const float* __restrict__ whh_f,
    const float* __restrict__ bih_f, const float* __restrict__ bhh_f,
    const float* __restrict__ wih_b, const float* __restrict__ whh_b,
    const float* __restrict__ bih_b, const float* __restrict__ bhh_b)
{
    __shared__ float xs[TT * FF];                 // 32 KB: full input row
    __shared__ __align__(16) float hs[2][H1P];    // double-buffered h (padded)

    const int tid = threadIdx.x;
    const int b   = blockIdx.x;
    const int dir = blockIdx.y;

    const float* wih = dir ? wih_b : wih_f;
    const float* whh = dir ? whh_b : whh_f;
    const float* bih = dir ? bih_b : bih_f;
    const float* bhh = dir ? bhh_b : bhh_f;

    for (int i = tid; i < TT * FF; i += 288)
        xs[i] = x[(size_t)b * TT * FF + i];
    if (tid < H1P) { hs[0][tid] = 0.0f; hs[1][tid] = 0.0f; }

    const int j = tid >> 2;          // cell
    const int g = tid & 3;           // gate
    const bool act = (j < H1);
    const int row = act ? (g * H1 + j) : 0;   // safe row for idle lanes

    float wi[FF];
    float wh[H1P];
    #pragma unroll
    for (int f = 0; f < FF; f++) wi[f] = wih[row * FF + f];
    #pragma unroll
    for (int k = 0; k < H1; k++) wh[k] = whh[row * H1 + k];
    wh[70] = 0.0f; wh[71] = 0.0f;
    const float bias = bih[row] + bhh[row];

    float c = 0.0f;
    int cur = 0;
    __syncthreads();

    for (int t = 0; t < TT; t++) {
        const int tt = dir ? (TT - 1 - t) : t;

        const float4* xr = (const float4*)&xs[tt * FF];
        float4 xa = xr[0];
        float4 xb = xr[1];
        float a0 = bias, a1 = 0.0f, a2 = 0.0f, a3 = 0.0f;
        a0 = fmaf(wi[0], xa.x, a0); a1 = fmaf(wi[1], xa.y, a1);
        a2 = fmaf(wi[2], xa.z, a2); a3 = fmaf(wi[3], xa.w, a3);
        a0 = fmaf(wi[4], xb.x, a0); a1 = fmaf(wi[5], xb.y, a1);
        a2 = fmaf(wi[6], xb.z, a2); a3 = fmaf(wi[7], xb.w, a3);

        const float4* h4 = (const float4*)hs[cur];
        #pragma unroll
        for (int k4 = 0; k4 < H1P / 4; k4++) {
            float4 h = h4[k4];
            a0 = fmaf(wh[4 * k4 + 0], h.x, a0);
            a1 = fmaf(wh[4 * k4 + 1], h.y, a1);
            a2 = fmaf(wh[4 * k4 + 2], h.z, a2);
            a3 = fmaf(wh[4 * k4 + 3], h.w, a3);
        }
        const float pre = (a0 + a1) + (a2 + a3);

        const float pf = __shfl_down_sync(0xffffffffu, pre, 1);
        const float pg = __shfl_down_sync(0xffffffffu, pre, 2);
        const float po = __shfl_down_sync(0xffffffffu, pre, 3);

        const int nxt = cur ^ 1;
        if (g == 0 && act) {
            const float gi = sigf(pre);
            const float gf = sigf(pf);
            const float gg = tanha(pg);
            const float go = sigf(po);
            c = fmaf(gf, c, gi * gg);
            const float h = go * tanha(c);
            hs[nxt][j] = h;
            g_h1[((size_t)b * TT + tt) * IN2 + dir * H1 + j] = h;
        }
        __syncthreads();
        cur = nxt;
    }
}

// ---------------------------------------------------------------------------
// Layer 2: one CTA per (batch, direction). 192 threads.
// Lane layout: j = tid>>3 (cell), g = (tid>>1)&3 (gate), e = tid&1 (half of
// the 164-wide dot). Halves combined with shfl_xor(1); gates gathered with
// shfl_down to the (g==0,e==0) lane. ONE barrier/step, input rows
// double-buffered from g_h1 with a register prefetch.
// ---------------------------------------------------------------------------
__global__ __launch_bounds__(192, 3) void lstm2_kernel(
    const float* __restrict__ wih_f, const float* __restrict__ whh_f,
    const float* __restrict__ bih_f, const float* __restrict__ bhh_f,
    const float* __restrict__ wih_b, const float* __restrict__ whh_b,
    const float* __restrict__ bih_b, const float* __restrict__ bhh_b)
{
    __shared__ __align__(16) float inbuf[2][IN2P];
    __shared__ __align__(16) float hs[2][H2P];

    const int tid = threadIdx.x;
    const int b   = blockIdx.x;
    const int dir = blockIdx.y;

    const float* wih = dir ? wih_b : wih_f;
    const float* whh = dir ? whh_b : whh_f;
    const float* bih = dir ? bih_b : bih_f;
    const float* bhh = dir ? bhh_b : bhh_f;

    const int j = tid >> 3;           // cell
    const int g = (tid >> 1) & 3;     // gate
    const int e = tid & 1;            // dot half
    const bool act = (j < H2);
    const int row = act ? (g * H2 + j) : 0;

    // Half of the input-projection weights: columns [e*72, e*72+72)
    float wi[IN2P / 2];
    #pragma unroll
    for (int k = 0; k < IN2P / 2; k++) {
        const int col = e * (IN2P / 2) + k;
        wi[k] = (col < IN2) ? wih[row * IN2 + col] : 0.0f;
    }
    // Half of the recurrent weights: columns [e*12, e*12+12)
    float wh[H2P / 2];
    #pragma unroll
    for (int k = 0; k < H2P / 2; k++) {
        const int col = e * (H2P / 2) + k;
        wh[k] = (col < H2) ? whh[row * H2 + col] : 0.0f;
    }
    const float bias = (e == 0) ? (bih[row] + bhh[row]) : 0.0f;

    if (tid < H2P) { hs[0][tid] = 0.0f; hs[1][tid] = 0.0f; }
    if (tid < 8) { inbuf[0][IN2 + (tid & 3)] = 0.0f; inbuf[1][IN2 + (tid & 3)] = 0.0f; }

    // preload first input row
    {
        const int tt0 = dir ? (TT - 1) : 0;
        const float* r0 = &g_h1[((size_t)b * TT + tt0) * IN2];
        if (tid < IN2) inbuf[0][tid] = r0[tid];
    }
    float c = 0.0f;
    int cur = 0;
    __syncthreads();

    for (int t = 0; t < TT; t++) {
        const int tt = dir ? (TT - 1 - t) : t;

        // prefetch next input row (latency hidden by compute below)
        float p0 = 0.0f;
        const bool have_next = (t + 1 < TT);
        if (have_next && tid < IN2) {
            const int tn = dir ? (TT - 2 - t) : (t + 1);
            p0 = g_h1[((size_t)b * TT + tn) * IN2 + tid];
        }

        float a0 = bias, a1 = 0.0f, a2 = 0.0f, a3 = 0.0f;
        const float4* in4 = (const float4*)&inbuf[cur][e * (IN2P / 2)];
        #pragma unroll
        for (int k4 = 0; k4 < IN2P / 8; k4++) {
            float4 v = in4[k4];
            a0 = fmaf(wi[4 * k4 + 0], v.x, a0);
            a1 = fmaf(wi[4 * k4 + 1], v.y, a1);
            a2 = fmaf(wi[4 * k4 + 2], v.z, a2);
            a3 = fmaf(wi[4 * k4 + 3], v.w, a3);
        }
        const float4* h4 = (const float4*)&hs[cur][e * (H2P / 2)];
        #pragma unroll
        for (int k4 = 0; k4 < H2P / 8; k4++) {
            float4 h = h4[k4];
            a0 = fmaf(wh[4 * k4 + 0], h.x, a0);
            a1 = fmaf(wh[4 * k4 + 1], h.y, a1);
            a2 = fmaf(wh[4 * k4 + 2], h.z, a2);
            a3 = fmaf(wh[4 * k4 + 3], h.w, a3);
        }
        float pre = (a0 + a1) + (a2 + a3);
        pre += __shfl_xor_sync(0xffffffffu, pre, 1);     // combine halves

        const float pf = __shfl_down_sync(0xffffffffu, pre, 2);
        const float pg = __shfl_down_sync(0xffffffffu, pre, 4);
        const float po = __shfl_down_sync(0xffffffffu, pre, 6);

        const int nxt = cur ^ 1;
        if (g == 0 && e == 0 && act) {
            const float gi = sigf(pre);
            const float gf = sigf(pf);
            const float gg = tanha(pg);
            const float go = sigf(po);
            c = fmaf(gf, c, gi * gg);
            const float h = go * tanha(c);
            hs[nxt][j] = h;
            g_h2[((size_t)b * TT + tt) * H22 + dir * H2 + j] = h;
        }
        if (have_next && tid < IN2) inbuf[nxt][tid] = p0;
        __syncthreads();
        cur = nxt;
    }
}

// ---------------------------------------------------------------------------
// Head MLP: 42 -> 30 relu -> 20 relu -> 1. One thread per (b,t).
// ---------------------------------------------------------------------------
__global__ __launch_bounds__(128) void head_kernel(
    const float* __restrict__ d1w, const float* __restrict__ d1b,
    const float* __restrict__ d2w, const float* __restrict__ d2b,
    const float* __restrict__ ow,  const float* __restrict__ ob,
    float* __restrict__ out)
{
    __shared__ float sv[128 * H22];
    __shared__ float w1[D1 * H22], b1[D1];
    __shared__ float w2[D2 * D1], b2[D2];
    __shared__ float wo[D2];
    __shared__ float obias;

    const int tid = threadIdx.x;
    const size_t base = (size_t)blockIdx.x * 128 * H22;

    for (int i = tid; i < 128 * H22; i += 128) sv[i] = g_h2[base + i];
    for (int i = tid; i < D1 * H22; i += 128) w1[i] = d1w[i];
    if (tid < D1) b1[tid] = d1b[tid];
    for (int i = tid; i < D2 * D1; i += 128) w2[i] = d2w[i];
    if (tid < D2) { b2[tid] = d2b[tid]; wo[tid] = ow[tid]; }
    if (tid == 0) obias = ob[0];
    __syncthreads();

    float v[H22];
    #pragma unroll
    for (int k = 0; k < H22; k++) v[k] = sv[tid * H22 + k];

    float a1[D1];
    #pragma unroll
    for (int jj = 0; jj < D1; jj++) {
        float s = b1[jj];
        #pragma unroll
        for (int k = 0; k < H22; k++) s = fmaf(w1[jj * H22 + k], v[k], s);
        a1[jj] = fmaxf(s, 0.0f);
    }
    float a2[D2];
    #pragma unroll
    for (int jj = 0; jj < D2; jj++) {
        float s = b2[jj];
        #pragma unroll
        for (int k = 0; k < D1; k++) s = fmaf(w2[jj * D1 + k], a1[k], s);
        a2[jj] = fmaxf(s, 0.0f);
    }
    float o = obias;
    #pragma unroll
    for (int k = 0; k < D2; k++) o = fmaf(wo[k], a2[k], o);

    out[(size_t)blockIdx.x * 128 + tid] = o;
}

// ---------------------------------------------------------------------------
extern "C" void kernel_launch(void* const* d_in, const int* in_sizes, int n_in,
                              void* d_out, int out_size)
{
    const float* x       = (const float*)d_in[0];
    const float* wih1_f  = (const float*)d_in[1];
    const float* whh1_f  = (const float*)d_in[2];
    const float* bih1_f  = (const float*)d_in[3];
    const float* bhh1_f  = (const float*)d_in[4];
    const float* wih1_b  = (const float*)d_in[5];
    const float* whh1_b  = (const float*)d_in[6];
    const float* bih1_b  = (const float*)d_in[7];
    const float* bhh1_b  = (const float*)d_in[8];
    const float* wih2_f  = (const float*)d_in[9];
    const float* whh2_f  = (const float*)d_in[10];
    const float* bih2_f  = (const float*)d_in[11];
    const float* bhh2_f  = (const float*)d_in[12];
    const float* wih2_b  = (const float*)d_in[13];
    const float* whh2_b  = (const float*)d_in[14];
    const float* bih2_b  = (const float*)d_in[15];
    const float* bhh2_b  = (const float*)d_in[16];
    const float* d1w     = (const float*)d_in[17];
    const float* d1b     = (const float*)d_in[18];
    const float* d2w     = (const float*)d_in[19];
    const float* d2b     = (const float*)d_in[20];
    const float* ow      = (const float*)d_in[21];
    const float* obv     = (const float*)d_in[22];
    float* out = (float*)d_out;

    dim3 grid_l(BB, 2);
    lstm1_kernel<<<grid_l, 288>>>(x, wih1_f, whh1_f, bih1_f, bhh1_f,
                                  wih1_b, whh1_b, bih1_b, bhh1_b);
    lstm2_kernel<<<grid_l, 192>>>(wih2_f, whh2_f, bih2_f, bhh2_f,
                                  wih2_b, whh2_b, bih2_b, bhh2_b);
    head_kernel<<<(BB * TT) / 128, 128>>>(d1w, d1b, d2w, d2b, ow, obv, out);
}

// round 4
// speedup vs baseline: 1.4902x; 1.0328x over previous
#include <cuda_runtime.h>
#include <math.h>

#define BB 512
#define TT 1024
#define FF 8
#define H1 70
#define H1P 72
#define G1 280
#define H2 21
#define H2P 24
#define G2 84
#define IN2 140
#define IN2P 144
#define D1 30
#define D2 20
#define H22 42

typedef unsigned long long u64;

// Scratch (allocation-free rule: __device__ globals)
__device__ float g_h1[(size_t)BB * TT * IN2];   // layer-1 bi-output, [b][t][140]
__device__ float g_h2[(size_t)BB * TT * H22];   // layer-2 bi-output, [b][t][42]

__device__ __forceinline__ float tanha(float x) {
    float y;
    asm("tanh.approx.f32 %0, %1;" : "=f"(y) : "f"(x));
    return y;
}
__device__ __forceinline__ float sigf(float x) {
    return fmaf(0.5f, tanha(0.5f * x), 0.5f);
}

// ---- packed f32x2 helpers -------------------------------------------------
__device__ __forceinline__ u64 pack2(float lo, float hi) {
    u64 r;
    asm("mov.b64 %0, {%1, %2};" : "=l"(r) : "f"(lo), "f"(hi));
    return r;
}
__device__ __forceinline__ void unpack2(u64 v, float& lo, float& hi) {
    asm("mov.b64 {%0, %1}, %2;" : "=f"(lo), "=f"(hi) : "l"(v));
}
__device__ __forceinline__ void ffma2(u64& d, u64 a, u64 b) {
    asm("fma.rn.f32x2 %0, %1, %2, %0;" : "+l"(d) : "l"(a), "l"(b));
}
__device__ __forceinline__ u64 addf2(u64 a, u64 b) {
    u64 r;
    asm("add.rn.f32x2 %0, %1, %2;" : "=l"(r) : "l"(a), "l"(b));
    return r;
}

// ---------------------------------------------------------------------------
// Layer 1: one CTA per (batch, direction). 288 threads.
// Thread tid: cell j = tid>>2, gate g = tid&3. 40 FFMA2 per step; gates
// gathered to the g==0 lane via shfl; double-buffered h; one barrier/step.
// ---------------------------------------------------------------------------
__global__ __launch_bounds__(288, 2) void lstm1_kernel(
    const float* __restrict__ x,
    const float* __restrict__ wih_f, const float* __restrict__ whh_f,
    const float* __restrict__ bih_f, const float* __restrict__ bhh_f,
    const float* __restrict__ wih_b, const float* __restrict__ whh_b,
    const float* __restrict__ bih_b, const float* __restrict__ bhh_b)
{
    __shared__ __align__(16) float xs[TT * FF];     // 32 KB
    __shared__ __align__(16) float hs[2][H1P];

    const int tid = threadIdx.x;
    const int b   = blockIdx.x;
    const int dir = blockIdx.y;

    const float* wih = dir ? wih_b : wih_f;
    const float* whh = dir ? whh_b : whh_f;
    const float* bih = dir ? bih_b : bih_f;
    const float* bhh = dir ? bhh_b : bhh_f;

    for (int i = tid; i < TT * FF; i += 288)
        xs[i] = x[(size_t)b * TT * FF + i];
    if (tid < H1P) { hs[0][tid] = 0.0f; hs[1][tid] = 0.0f; }

    const int j = tid >> 2;
    const int g = tid & 3;
    const bool act = (j < H1);
    const int row = act ? (g * H1 + j) : 0;

    u64 wip[4];
    u64 whp[36];
    #pragma unroll
    for (int f = 0; f < 4; f++)
        wip[f] = pack2(wih[row * FF + 2 * f], wih[row * FF + 2 * f + 1]);
    #pragma unroll
    for (int k = 0; k < 35; k++)
        whp[k] = pack2(whh[row * H1 + 2 * k], whh[row * H1 + 2 * k + 1]);
    whp[35] = 0ull;
    const float bias = bih[row] + bhh[row];

    float c = 0.0f;
    int cur = 0;
    const int step = dir ? -1 : 1;
    int tt = dir ? (TT - 1) : 0;
    const float* xp = &xs[tt * FF];
    float* op = &g_h1[((size_t)b * TT + tt) * IN2 + dir * H1 + j];
    const int xstep = step * FF;
    const long ostep = (long)step * IN2;
    __syncthreads();

    for (int t = 0; t < TT; t++) {
        u64 acc0 = pack2(bias, 0.0f);
        u64 acc1 = 0ull, acc2 = 0ull, acc3 = 0ull;

        const ulonglong2* xr = (const ulonglong2*)xp;
        ulonglong2 xA = xr[0], xB = xr[1];
        ffma2(acc0, wip[0], xA.x); ffma2(acc1, wip[1], xA.y);
        ffma2(acc2, wip[2], xB.x); ffma2(acc3, wip[3], xB.y);

        const ulonglong2* h2p = (const ulonglong2*)hs[cur];
        #pragma unroll
        for (int k = 0; k < 9; k++) {
            ulonglong2 ha = h2p[2 * k];
            ulonglong2 hb = h2p[2 * k + 1];
            ffma2(acc0, whp[4 * k + 0], ha.x);
            ffma2(acc1, whp[4 * k + 1], ha.y);
            ffma2(acc2, whp[4 * k + 2], hb.x);
            ffma2(acc3, whp[4 * k + 3], hb.y);
        }
        u64 s = addf2(addf2(acc0, acc1), addf2(acc2, acc3));
        float lo, hi;
        unpack2(s, lo, hi);
        const float pre = lo + hi;

        const float pf = __shfl_down_sync(0xffffffffu, pre, 1);
        const float pg = __shfl_down_sync(0xffffffffu, pre, 2);
        const float po = __shfl_down_sync(0xffffffffu, pre, 3);

        const int nxt = cur ^ 1;
        if (g == 0 && act) {
            const float gi = sigf(pre);
            const float gf = sigf(pf);
            const float gg = tanha(pg);
            const float go = sigf(po);
            c = fmaf(gf, c, gi * gg);
            const float h = go * tanha(c);
            hs[nxt][j] = h;
            *op = h;
        }
        __syncthreads();
        cur = nxt;
        xp += xstep;
        op += ostep;
    }
}

// ---------------------------------------------------------------------------
// Layer 2: one CTA per (batch, direction). 192 threads.
// Thread tid: cell j = tid>>3, gate g = (tid>>1)&3, half e = tid&1.
// 42 FFMA2 per step per thread; halves combined with shfl_xor(1).
// ---------------------------------------------------------------------------
__global__ __launch_bounds__(192, 3) void lstm2_kernel(
    const float* __restrict__ wih_f, const float* __restrict__ whh_f,
    const float* __restrict__ bih_f, const float* __restrict__ bhh_f,
    const float* __restrict__ wih_b, const float* __restrict__ whh_b,
    const float* __restrict__ bih_b, const float* __restrict__ bhh_b)
{
    __shared__ __align__(16) float inbuf[2][IN2P];
    __shared__ __align__(16) float hs[2][H2P];

    const int tid = threadIdx.x;
    const int b   = blockIdx.x;
    const int dir = blockIdx.y;

    const float* wih = dir ? wih_b : wih_f;
    const float* whh = dir ? whh_b : whh_f;
    const float* bih = dir ? bih_b : bih_f;
    const float* bhh = dir ? bhh_b : bhh_f;

    const int j = tid >> 3;
    const int g = (tid >> 1) & 3;
    const int e = tid & 1;
    const bool act = (j < H2);
    const int row = act ? (g * H2 + j) : 0;

    u64 wip[36];                       // 72 input weights for this half
    #pragma unroll
    for (int k = 0; k < 36; k++) {
        const int c0 = e * 72 + 2 * k;
        const int c1 = c0 + 1;
        wip[k] = pack2((c0 < IN2) ? wih[row * IN2 + c0] : 0.0f,
                       (c1 < IN2) ? wih[row * IN2 + c1] : 0.0f);
    }
    u64 whp[6];                        // 12 recurrent weights for this half
    #pragma unroll
    for (int k = 0; k < 6; k++) {
        const int c0 = e * 12 + 2 * k;
        const int c1 = c0 + 1;
        whp[k] = pack2((c0 < H2) ? whh[row * H2 + c0] : 0.0f,
                       (c1 < H2) ? whh[row * H2 + c1] : 0.0f);
    }
    const float bias = (e == 0) ? (bih[row] + bhh[row]) : 0.0f;

    if (tid < H2P) { hs[0][tid] = 0.0f; hs[1][tid] = 0.0f; }
    if (tid < 4) { inbuf[0][IN2 + tid] = 0.0f; inbuf[1][IN2 + tid] = 0.0f; }

    {
        const int tt0 = dir ? (TT - 1) : 0;
        const float* r0 = &g_h1[((size_t)b * TT + tt0) * IN2];
        if (tid < IN2) inbuf[0][tid] = r0[tid];
    }
    float c = 0.0f;
    int cur = 0;
    const int step = dir ? -1 : 1;
    const int tt0 = dir ? (TT - 1) : 0;
    float* op = &g_h2[((size_t)b * TT + tt0) * H22 + dir * H2 + j];
    const long ostep = (long)step * H22;
    const float* ip = &g_h1[((size_t)b * TT + tt0 + step) * IN2 + tid];
    const long istep = (long)step * IN2;
    __syncthreads();

    for (int t = 0; t < TT; t++) {
        float p0 = 0.0f;
        const bool have_next = (t + 1 < TT);
        if (have_next && tid < IN2) p0 = *ip;

        u64 acc0 = pack2(bias, 0.0f);
        u64 acc1 = 0ull, acc2 = 0ull, acc3 = 0ull;

        const ulonglong2* in2 = (const ulonglong2*)&inbuf[cur][e * 72];
        #pragma unroll
        for (int k = 0; k < 9; k++) {
            ulonglong2 va = in2[2 * k];
            ulonglong2 vb = in2[2 * k + 1];
            ffma2(acc0, wip[4 * k + 0], va.x);
            ffma2(acc1, wip[4 * k + 1], va.y);
            ffma2(acc2, wip[4 * k + 2], vb.x);
            ffma2(acc3, wip[4 * k + 3], vb.y);
        }
        const ulonglong2* h2p = (const ulonglong2*)&hs[cur][e * 12];
        {
            ulonglong2 ha = h2p[0];
            ulonglong2 hb = h2p[1];
            ulonglong2 hc = h2p[2];
            ffma2(acc0, whp[0], ha.x);
            ffma2(acc1, whp[1], ha.y);
            ffma2(acc2, whp[2], hb.x);
            ffma2(acc3, whp[3], hb.y);
            ffma2(acc0, whp[4], hc.x);
            ffma2(acc1, whp[5], hc.y);
        }
        u64 s = addf2(addf2(acc0, acc1), addf2(acc2, acc3));
        float lo, hi;
        unpack2(s, lo, hi);
        float pre = lo + hi;
        pre += __shfl_xor_sync(0xffffffffu, pre, 1);

        const float pf = __shfl_down_sync(0xffffffffu, pre, 2);
        const float pg = __shfl_down_sync(0xffffffffu, pre, 4);
        const float po = __shfl_down_sync(0xffffffffu, pre, 6);

        const int nxt = cur ^ 1;
        if (g == 0 && e == 0 && act) {
            const float gi = sigf(pre);
            const float gf = sigf(pf);
            const float gg = tanha(pg);
            const float go = sigf(po);
            c = fmaf(gf, c, gi * gg);
            const float h = go * tanha(c);
            hs[nxt][j] = h;
            *op = h;
        }
        if (have_next && tid < IN2) inbuf[nxt][tid] = p0;
        __syncthreads();
        cur = nxt;
        op += ostep;
        ip += istep;
    }
}

// ---------------------------------------------------------------------------
// Head MLP: 42 -> 30 relu -> 20 relu -> 1. One thread per (b,t), f32x2 dots.
// ---------------------------------------------------------------------------
__global__ __launch_bounds__(128) void head_kernel(
    const float* __restrict__ d1w, const float* __restrict__ d1b,
    const float* __restrict__ d2w, const float* __restrict__ d2b,
    const float* __restrict__ ow,  const float* __restrict__ ob,
    float* __restrict__ out)
{
    __shared__ __align__(16) float sv[128 * H22];
    __shared__ __align__(8) float w1[D1 * H22];
    __shared__ float b1[D1];
    __shared__ __align__(8) float w2[D2 * D1];
    __shared__ float b2[D2];
    __shared__ float wo[D2];
    __shared__ float obias;

    const int tid = threadIdx.x;
    const size_t base = (size_t)blockIdx.x * 128 * H22;

    for (int i = tid; i < 128 * H22; i += 128) sv[i] = g_h2[base + i];
    for (int i = tid; i < D1 * H22; i += 128) w1[i] = d1w[i];
    if (tid < D1) b1[tid] = d1b[tid];
    for (int i = tid; i < D2 * D1; i += 128) w2[i] = d2w[i];
    if (tid < D2) { b2[tid] = d2b[tid]; wo[tid] = ow[tid]; }
    if (tid == 0) obias = ob[0];
    __syncthreads();

    u64 v[21];                               // 42 floats, 8B-aligned rows
    const u64* svr = (const u64*)&sv[tid * H22];
    #pragma unroll
    for (int k = 0; k < 21; k++) v[k] = svr[k];

    float a1[D1];
    #pragma unroll
    for (int jj = 0; jj < D1; jj++) {
        const u64* wr = (const u64*)&w1[jj * H22];
        u64 acc0 = pack2(b1[jj], 0.0f), acc1 = 0ull;
        #pragma unroll
        for (int k = 0; k < 21; k += 2) {
            ffma2(acc0, wr[k], v[k]);
            if (k + 1 < 21) ffma2(acc1, wr[k + 1], v[k + 1]);
        }
        float lo, hi;
        unpack2(addf2(acc0, acc1), lo, hi);
        a1[jj] = fmaxf(lo + hi, 0.0f);
    }
    u64 a1p[15];
    #pragma unroll
    for (int k = 0; k < 15; k++) a1p[k] = pack2(a1[2 * k], a1[2 * k + 1]);

    float a2[D2];
    #pragma unroll
    for (int jj = 0; jj < D2; jj++) {
        const u64* wr = (const u64*)&w2[jj * D1];
        u64 acc0 = pack2(b2[jj], 0.0f), acc1 = 0ull;
        #pragma unroll
        for (int k = 0; k < 15; k += 2) {
            ffma2(acc0, wr[k], a1p[k]);
            if (k + 1 < 15) ffma2(acc1, wr[k + 1], a1p[k + 1]);
        }
        float lo, hi;
        unpack2(addf2(acc0, acc1), lo, hi);
        a2[jj] = fmaxf(lo + hi, 0.0f);
    }
    float o = obias;
    #pragma unroll
    for (int k = 0; k < D2; k++) o = fmaf(wo[k], a2[k], o);

    out[(size_t)blockIdx.x * 128 + tid] = o;
}

// ---------------------------------------------------------------------------
extern "C" void kernel_launch(void* const* d_in, const int* in_sizes, int n_in,
                              void* d_out, int out_size)
{
    const float* x       = (const float*)d_in[0];
    const float* wih1_f  = (const float*)d_in[1];
    const float* whh1_f  = (const float*)d_in[2];
    const float* bih1_f  = (const float*)d_in[3];
    const float* bhh1_f  = (const float*)d_in[4];
    const float* wih1_b  = (const float*)d_in[5];
    const float* whh1_b  = (const float*)d_in[6];
    const float* bih1_b  = (const float*)d_in[7];
    const float* bhh1_b  = (const float*)d_in[8];
    const float* wih2_f  = (const float*)d_in[9];
    const float* whh2_f  = (const float*)d_in[10];
    const float* bih2_f  = (const float*)d_in[11];
    const float* bhh2_f  = (const float*)d_in[12];
    const float* wih2_b  = (const float*)d_in[13];
    const float* whh2_b  = (const float*)d_in[14];
    const float* bih2_b  = (const float*)d_in[15];
    const float* bhh2_b  = (const float*)d_in[16];
    const float* d1w     = (const float*)d_in[17];
    const float* d1b     = (const float*)d_in[18];
    const float* d2w     = (const float*)d_in[19];
    const float* d2b     = (const float*)d_in[20];
    const float* ow      = (const float*)d_in[21];
    const float* obv     = (const float*)d_in[22];
    float* out = (float*)d_out;

    dim3 grid_l(BB, 2);
    lstm1_kernel<<<grid_l, 288>>>(x, wih1_f, whh1_f, bih1_f, bhh1_f,
                                  wih1_b, whh1_b, bih1_b, bhh1_b);
    lstm2_kernel<<<grid_l, 192>>>(wih2_f, whh2_f, bih2_f, bhh2_f,
                                  wih2_b, whh2_b, bih2_b, bhh2_b);
    head_kernel<<<(BB * TT) / 128, 128>>>(d1w, d1b, d2w, d2b, ow, obv, out);
}

// round 5
// speedup vs baseline: 1.8169x; 1.2192x over previous
#include <cuda_runtime.h>
#include <math.h>

#define BB 512
#define TT 1024
#define FF 8
#define H1 70
#define H1P 72
#define G1 280
#define H2 21
#define H2P 24
#define G2 84
#define IN2 140
#define IN2P 144
#define D1 30
#define D2 20
#define H22 42

typedef unsigned long long u64;

// Scratch (allocation-free rule: __device__ globals)
__device__ float g_h1[(size_t)BB * TT * IN2];   // layer-1 bi-output, [b][t][140]
__device__ float g_h2[(size_t)BB * TT * H22];   // layer-2 bi-output, [b][t][42]

__device__ __forceinline__ float tanha(float x) {
    float y;
    asm("tanh.approx.f32 %0, %1;" : "=f"(y) : "f"(x));
    return y;
}
__device__ __forceinline__ float sigf(float x) {
    return fmaf(0.5f, tanha(0.5f * x), 0.5f);
}

// ---- packed f32x2 helpers -------------------------------------------------
__device__ __forceinline__ u64 pack2(float lo, float hi) {
    u64 r;
    asm("mov.b64 %0, {%1, %2};" : "=l"(r) : "f"(lo), "f"(hi));
    return r;
}
__device__ __forceinline__ void unpack2(u64 v, float& lo, float& hi) {
    asm("mov.b64 {%0, %1}, %2;" : "=f"(lo), "=f"(hi) : "l"(v));
}
__device__ __forceinline__ void ffma2(u64& d, u64 a, u64 b) {
    asm("fma.rn.f32x2 %0, %1, %2, %0;" : "+l"(d) : "l"(a), "l"(b));
}
__device__ __forceinline__ u64 addf2(u64 a, u64 b) {
    u64 r;
    asm("add.rn.f32x2 %0, %1, %2;" : "=l"(r) : "l"(a), "l"(b));
    return r;
}

// ---------------------------------------------------------------------------
// Layer 1: one CTA per (batch, direction). 288 threads = 72 cells x 4 lanes.
// Lane (j, p, e): cell j, gate-pair p (p=0 -> i,f ; p=1 -> g,o), k-half e.
// Each thread: 2 gate rows x half-k -> 40 FFMA2, 10 LDS.128 per step.
// Halves combine via shfl_xor(1); pairs exchange via shfl_xor(2); all 4
// lanes compute the cell update redundantly; lane (tid&3)==0 writes.
// ---------------------------------------------------------------------------
__global__ __launch_bounds__(288, 2) void lstm1_kernel(
    const float* __restrict__ x,
    const float* __restrict__ wih_f, const float* __restrict__ whh_f,
    const float* __restrict__ bih_f, const float* __restrict__ bhh_f,
    const float* __restrict__ wih_b, const float* __restrict__ whh_b,
    const float* __restrict__ bih_b, const float* __restrict__ bhh_b)
{
    __shared__ __align__(16) float xs[TT * FF];     // 32 KB
    __shared__ __align__(16) float hs[2][H1P];

    const int tid = threadIdx.x;
    const int b   = blockIdx.x;
    const int dir = blockIdx.y;

    const float* wih = dir ? wih_b : wih_f;
    const float* whh = dir ? whh_b : whh_f;
    const float* bih = dir ? bih_b : bih_f;
    const float* bhh = dir ? bhh_b : bhh_f;

    for (int i = tid; i < TT * FF; i += 288)
        xs[i] = x[(size_t)b * TT * FF + i];
    if (tid < H1P) { hs[0][tid] = 0.0f; hs[1][tid] = 0.0f; }

    const int j = tid >> 2;
    const int p = (tid >> 1) & 1;
    const int e = tid & 1;
    const bool act = (j < H1);
    const int r0 = act ? ((2 * p) * H1 + j) : 0;
    const int r1 = act ? ((2 * p + 1) * H1 + j) : 0;

    // recurrent weights, half-k: padded cols [36e, 36e+36)
    u64 w0[18], w1[18];
    #pragma unroll
    for (int k = 0; k < 18; k++) {
        const int c0 = 36 * e + 2 * k, c1 = c0 + 1;
        w0[k] = pack2((c0 < H1) ? whh[r0 * H1 + c0] : 0.0f,
                      (c1 < H1) ? whh[r0 * H1 + c1] : 0.0f);
        w1[k] = pack2((c0 < H1) ? whh[r1 * H1 + c0] : 0.0f,
                      (c1 < H1) ? whh[r1 * H1 + c1] : 0.0f);
    }
    // input weights, quarter-x: cols [4e, 4e+4)
    u64 xw0[2], xw1[2];
    #pragma unroll
    for (int k = 0; k < 2; k++) {
        const int c0 = 4 * e + 2 * k;
        xw0[k] = pack2(wih[r0 * FF + c0], wih[r0 * FF + c0 + 1]);
        xw1[k] = pack2(wih[r1 * FF + c0], wih[r1 * FF + c0 + 1]);
    }
    const float bias0 = (e == 0) ? (bih[r0] + bhh[r0]) : 0.0f;
    const float bias1 = (e == 0) ? (bih[r1] + bhh[r1]) : 0.0f;

    float c = 0.0f;
    int cur = 0;
    const int step = dir ? -1 : 1;
    const int tt0 = dir ? (TT - 1) : 0;
    const float* xp = &xs[tt0 * FF + 4 * e];
    float* optr = &g_h1[((size_t)b * TT + tt0) * IN2 + dir * H1 + j];
    const int xstep = step * FF;
    const long ostep = (long)step * IN2;
    __syncthreads();

    for (int t = 0; t < TT; t++) {
        const ulonglong2 xv = *(const ulonglong2*)xp;
        u64 a00 = pack2(bias0, 0.0f), a01 = 0ull;
        u64 a10 = pack2(bias1, 0.0f), a11 = 0ull;
        ffma2(a00, xw0[0], xv.x); ffma2(a01, xw0[1], xv.y);
        ffma2(a10, xw1[0], xv.x); ffma2(a11, xw1[1], xv.y);

        const ulonglong2* hp = (const ulonglong2*)&hs[cur][36 * e];
        #pragma unroll
        for (int k = 0; k < 9; k++) {
            const ulonglong2 hv = hp[k];
            ffma2(a00, w0[2 * k],     hv.x);
            ffma2(a01, w0[2 * k + 1], hv.y);
            ffma2(a10, w1[2 * k],     hv.x);
            ffma2(a11, w1[2 * k + 1], hv.y);
        }
        float lo, hi;
        unpack2(addf2(a00, a01), lo, hi);
        float s0 = lo + hi;
        unpack2(addf2(a10, a11), lo, hi);
        float s1 = lo + hi;

        s0 += __shfl_xor_sync(0xffffffffu, s0, 1);   // combine k-halves
        s1 += __shfl_xor_sync(0xffffffffu, s1, 1);
        const float o0 = __shfl_xor_sync(0xffffffffu, s0, 2);  // swap gate pair
        const float o1 = __shfl_xor_sync(0xffffffffu, s1, 2);

        const float pi = p ? o0 : s0;
        const float pf = p ? o1 : s1;
        const float pg = p ? s0 : o0;
        const float po = p ? s1 : o1;

        const float gi = sigf(pi);
        const float gf = sigf(pf);
        const float gg = tanha(pg);
        const float go = sigf(po);
        c = fmaf(gf, c, gi * gg);
        const float hval = go * tanha(c);

        const int nxt = cur ^ 1;
        if (((tid & 3) == 0) && act) {
            hs[nxt][j] = hval;
            *optr = hval;
        }
        __syncthreads();
        cur = nxt;
        xp += xstep;
        optr += ostep;
    }
}

// ---------------------------------------------------------------------------
// Layer 2: one CTA per (batch, direction). 192 threads = 24 cells x 8 lanes.
// Lane (j, p, q): cell j, gate-pair p, k-quarter q. Each thread: 2 rows x
// quarter-k -> 42 FFMA2, ~12 LDS per step. Quarters combine via shfl_xor(1,2);
// pairs exchange via shfl_xor(4); all 8 lanes compute the update redundantly.
// ---------------------------------------------------------------------------
__global__ __launch_bounds__(192, 2) void lstm2_kernel(
    const float* __restrict__ wih_f, const float* __restrict__ whh_f,
    const float* __restrict__ bih_f, const float* __restrict__ bhh_f,
    const float* __restrict__ wih_b, const float* __restrict__ whh_b,
    const float* __restrict__ bih_b, const float* __restrict__ bhh_b)
{
    __shared__ __align__(16) float inbuf[2][IN2P];
    __shared__ __align__(16) float hs[2][H2P];

    const int tid = threadIdx.x;
    const int b   = blockIdx.x;
    const int dir = blockIdx.y;

    const float* wih = dir ? wih_b : wih_f;
    const float* whh = dir ? whh_b : whh_f;
    const float* bih = dir ? bih_b : bih_f;
    const float* bhh = dir ? bhh_b : bhh_f;

    const int j = tid >> 3;          // cell 0..23
    const int p = (tid >> 2) & 1;    // gate pair
    const int q = tid & 3;           // k quarter
    const bool act = (j < H2);
    const int r0 = act ? ((2 * p) * H2 + j) : 0;
    const int r1 = act ? ((2 * p + 1) * H2 + j) : 0;

    // input weights, quarter: padded cols [36q, 36q+36)
    u64 wi0[18], wi1[18];
    #pragma unroll
    for (int k = 0; k < 18; k++) {
        const int c0 = 36 * q + 2 * k, c1 = c0 + 1;
        wi0[k] = pack2((c0 < IN2) ? wih[r0 * IN2 + c0] : 0.0f,
                       (c1 < IN2) ? wih[r0 * IN2 + c1] : 0.0f);
        wi1[k] = pack2((c0 < IN2) ? wih[r1 * IN2 + c0] : 0.0f,
                       (c1 < IN2) ? wih[r1 * IN2 + c1] : 0.0f);
    }
    // recurrent weights, quarter: padded cols [6q, 6q+6)
    u64 wh0[3], wh1[3];
    #pragma unroll
    for (int k = 0; k < 3; k++) {
        const int c0 = 6 * q + 2 * k, c1 = c0 + 1;
        wh0[k] = pack2((c0 < H2) ? whh[r0 * H2 + c0] : 0.0f,
                       (c1 < H2) ? whh[r0 * H2 + c1] : 0.0f);
        wh1[k] = pack2((c0 < H2) ? whh[r1 * H2 + c0] : 0.0f,
                       (c1 < H2) ? whh[r1 * H2 + c1] : 0.0f);
    }
    const float bias0 = (q == 0) ? (bih[r0] + bhh[r0]) : 0.0f;
    const float bias1 = (q == 0) ? (bih[r1] + bhh[r1]) : 0.0f;

    if (tid < H2P) { hs[0][tid] = 0.0f; hs[1][tid] = 0.0f; }
    if (tid < 4) { inbuf[0][IN2 + tid] = 0.0f; inbuf[1][IN2 + tid] = 0.0f; }

    const int step = dir ? -1 : 1;
    const int tt0 = dir ? (TT - 1) : 0;
    {
        const float* r = &g_h1[((size_t)b * TT + tt0) * IN2];
        if (tid < IN2) inbuf[0][tid] = r[tid];
    }
    float c = 0.0f;
    int cur = 0;
    float* optr = &g_h2[((size_t)b * TT + tt0) * H22 + dir * H2 + j];
    const long ostep = (long)step * H22;
    const float* ipp = &g_h1[((size_t)b * TT + tt0 + step) * IN2 + tid];
    const long istep = (long)step * IN2;
    __syncthreads();

    for (int t = 0; t < TT; t++) {
        float pf0 = 0.0f;
        const bool have_next = (t + 1 < TT);
        if (have_next && tid < IN2) pf0 = *ipp;

        u64 a00 = pack2(bias0, 0.0f), a01 = 0ull;
        u64 a10 = pack2(bias1, 0.0f), a11 = 0ull;

        const ulonglong2* vp = (const ulonglong2*)&inbuf[cur][36 * q];
        #pragma unroll
        for (int k = 0; k < 9; k++) {
            const ulonglong2 vv = vp[k];
            ffma2(a00, wi0[2 * k],     vv.x);
            ffma2(a01, wi0[2 * k + 1], vv.y);
            ffma2(a10, wi1[2 * k],     vv.x);
            ffma2(a11, wi1[2 * k + 1], vv.y);
        }
        const u64* hp = (const u64*)&hs[cur][6 * q];
        {
            const u64 h0 = hp[0], h1 = hp[1], h2v = hp[2];
            ffma2(a00, wh0[0], h0);
            ffma2(a01, wh0[1], h1);
            ffma2(a00, wh0[2], h2v);
            ffma2(a10, wh1[0], h0);
            ffma2(a11, wh1[1], h1);
            ffma2(a10, wh1[2], h2v);
        }
        float lo, hi;
        unpack2(addf2(a00, a01), lo, hi);
        float s0 = lo + hi;
        unpack2(addf2(a10, a11), lo, hi);
        float s1 = lo + hi;

        s0 += __shfl_xor_sync(0xffffffffu, s0, 1);
        s1 += __shfl_xor_sync(0xffffffffu, s1, 1);
        s0 += __shfl_xor_sync(0xffffffffu, s0, 2);
        s1 += __shfl_xor_sync(0xffffffffu, s1, 2);
        const float o0 = __shfl_xor_sync(0xffffffffu, s0, 4);
        const float o1 = __shfl_xor_sync(0xffffffffu, s1, 4);

        const float pi = p ? o0 : s0;
        const float pf = p ? o1 : s1;
        const float pg = p ? s0 : o0;
        const float po = p ? s1 : o1;

        const float gi = sigf(pi);
        const float gf = sigf(pf);
        const float gg = tanha(pg);
        const float go = sigf(po);
        c = fmaf(gf, c, gi * gg);
        const float hval = go * tanha(c);

        const int nxt = cur ^ 1;
        if (((tid & 7) == 0) && act) {
            hs[nxt][j] = hval;
            *optr = hval;
        }
        if (have_next && tid < IN2) inbuf[nxt][tid] = pf0;
        __syncthreads();
        cur = nxt;
        optr += ostep;
        ipp += istep;
    }
}

// ---------------------------------------------------------------------------
// Head MLP: 42 -> 30 relu -> 20 relu -> 1. One thread per (b,t), f32x2 dots.
// ---------------------------------------------------------------------------
__global__ __launch_bounds__(128) void head_kernel(
    const float* __restrict__ d1w, const float* __restrict__ d1b,
    const float* __restrict__ d2w, const float* __restrict__ d2b,
    const float* __restrict__ ow,  const float* __restrict__ ob,
    float* __restrict__ out)
{
    __shared__ __align__(16) float sv[128 * H22];
    __shared__ __align__(8) float w1[D1 * H22];
    __shared__ float b1[D1];
    __shared__ __align__(8) float w2[D2 * D1];
    __shared__ float b2[D2];
    __shared__ float wo[D2];
    __shared__ float obias;

    const int tid = threadIdx.x;
    const size_t base = (size_t)blockIdx.x * 128 * H22;

    for (int i = tid; i < 128 * H22; i += 128) sv[i] = g_h2[base + i];
    for (int i = tid; i < D1 * H22; i += 128) w1[i] = d1w[i];
    if (tid < D1) b1[tid] = d1b[tid];
    for (int i = tid; i < D2 * D1; i += 128) w2[i] = d2w[i];
    if (tid < D2) { b2[tid] = d2b[tid]; wo[tid] = ow[tid]; }
    if (tid == 0) obias = ob[0];
    __syncthreads();

    u64 v[21];
    const u64* svr = (const u64*)&sv[tid * H22];
    #pragma unroll
    for (int k = 0; k < 21; k++) v[k] = svr[k];

    float a1[D1];
    #pragma unroll
    for (int jj = 0; jj < D1; jj++) {
        const u64* wr = (const u64*)&w1[jj * H22];
        u64 acc0 = pack2(b1[jj], 0.0f), acc1 = 0ull;
        #pragma unroll
        for (int k = 0; k < 21; k += 2) {
            ffma2(acc0, wr[k], v[k]);
            if (k + 1 < 21) ffma2(acc1, wr[k + 1], v[k + 1]);
        }
        float lo, hi;
        unpack2(addf2(acc0, acc1), lo, hi);
        a1[jj] = fmaxf(lo + hi, 0.0f);
    }
    u64 a1p[15];
    #pragma unroll
    for (int k = 0; k < 15; k++) a1p[k] = pack2(a1[2 * k], a1[2 * k + 1]);

    float a2[D2];
    #pragma unroll
    for (int jj = 0; jj < D2; jj++) {
        const u64* wr = (const u64*)&w2[jj * D1];
        u64 acc0 = pack2(b2[jj], 0.0f), acc1 = 0ull;
        #pragma unroll
        for (int k = 0; k < 15; k += 2) {
            ffma2(acc0, wr[k], a1p[k]);
            if (k + 1 < 15) ffma2(acc1, wr[k + 1], a1p[k + 1]);
        }
        float lo, hi;
        unpack2(addf2(acc0, acc1), lo, hi);
        a2[jj] = fmaxf(lo + hi, 0.0f);
    }
    float o = obias;
    #pragma unroll
    for (int k = 0; k < D2; k++) o = fmaf(wo[k], a2[k], o);

    out[(size_t)blockIdx.x * 128 + tid] = o;
}

// ---------------------------------------------------------------------------
extern "C" void kernel_launch(void* const* d_in, const int* in_sizes, int n_in,
                              void* d_out, int out_size)
{
    const float* x       = (const float*)d_in[0];
    const float* wih1_f  = (const float*)d_in[1];
    const float* whh1_f  = (const float*)d_in[2];
    const float* bih1_f  = (const float*)d_in[3];
    const float* bhh1_f  = (const float*)d_in[4];
    const float* wih1_b  = (const float*)d_in[5];
    const float* whh1_b  = (const float*)d_in[6];
    const float* bih1_b  = (const float*)d_in[7];
    const float* bhh1_b  = (const float*)d_in[8];
    const float* wih2_f  = (const float*)d_in[9];
    const float* whh2_f  = (const float*)d_in[10];
    const float* bih2_f  = (const float*)d_in[11];
    const float* bhh2_f  = (const float*)d_in[12];
    const float* wih2_b  = (const float*)d_in[13];
    const float* whh2_b  = (const float*)d_in[14];
    const float* bih2_b  = (const float*)d_in[15];
    const float* bhh2_b  = (const float*)d_in[16];
    const float* d1w     = (const float*)d_in[17];
    const float* d1b     = (const float*)d_in[18];
    const float* d2w     = (const float*)d_in[19];
    const float* d2b     = (const float*)d_in[20];
    const float* ow      = (const float*)d_in[21];
    const float* obv     = (const float*)d_in[22];
    float* out = (float*)d_out;

    dim3 grid_l(BB, 2);
    lstm1_kernel<<<grid_l, 288>>>(x, wih1_f, whh1_f, bih1_f, bhh1_f,
                                  wih1_b, whh1_b, bih1_b, bhh1_b);
    lstm2_kernel<<<grid_l, 192>>>(wih2_f, whh2_f, bih2_f, bhh2_f,
                                  wih2_b, whh2_b, bih2_b, bhh2_b);
    head_kernel<<<(BB * TT) / 128, 128>>>(d1w, d1b, d2w, d2b, ow, obv, out);
}